// round 10
// baseline (speedup 1.0000x reference)
#include <cuda_runtime.h>
#include <math.h>

// ---------------- scratch (device globals; no allocation allowed) ----------
__device__ float g_scores[512];         // attn logits
__device__ float g_ctx_part[8 * 2048];  // split-K context partials
__device__ float g_ctx[2048];           // reduced context
__device__ float g_x[2048];             // relu(attn_combine)
__device__ float g_gates[12288];        // gi[0:6144), gh[6144:12288)
__device__ float g_lmax[512];           // per-block logits max partials
__device__ float g_lsum[512];           // per-block sumexp partials
__device__ int   g_cnt_ctx;             // ctx arrival counter (self-resetting)

#define H 2048
#define V 50257
#define L 512
#define NB_LOGITS 444
#define NB_GATES 444

__device__ __forceinline__ float warpSum(float v) {
#pragma unroll
    for (int o = 16; o; o >>= 1) v += __shfl_down_sync(0xffffffffu, v, o);
    return v;
}

// ---- 8-float4 chunk helpers (A/B pipelined dot for 2H rows) ----
__device__ __forceinline__ void loadChunk(float4* dst, const float4* __restrict__ w4,
                                          int lane) {
#pragma unroll
    for (int j = 0; j < 8; j++) dst[j] = __ldcs(&w4[lane + 32 * j]);
}
__device__ __forceinline__ float dotChunk(const float4* wr, const float4* __restrict__ sv,
                                          int lane) {
    float a0 = 0.f, a1 = 0.f, a2 = 0.f, a3 = 0.f;
#pragma unroll
    for (int j = 0; j < 8; j++) {
        float4 v = sv[lane + 32 * j];
        a0 += wr[j].x * v.x;
        a1 += wr[j].y * v.y;
        a2 += wr[j].z * v.z;
        a3 += wr[j].w * v.w;
    }
    return (a0 + a1) + (a2 + a3);
}
template <int NC>
__device__ __forceinline__ float warpRowDot(const float4* __restrict__ w4,
                                            const float4* __restrict__ sv,
                                            int lane) {
    float4 A[8], B[8];
    loadChunk(A, w4, lane);
    float acc = 0.f;
#pragma unroll
    for (int c = 0; c < NC; c++) {
        float4* cur = (c & 1) ? B : A;
        float4* nxt = (c & 1) ? A : B;
        if (c + 1 < NC) loadChunk(nxt, w4 + (c + 1) * 256, lane);
        acc += dotChunk(cur, sv + c * 256, lane);
    }
    return warpSum(acc);
}

// ---- 16-float4 full-row helpers (H rows: gates, logits) ----
__device__ __forceinline__ void load16(float4* dst, const float4* __restrict__ w4,
                                       int lane) {
#pragma unroll
    for (int j = 0; j < 16; j++) dst[j] = __ldcs(&w4[lane + 32 * j]);
}
__device__ __forceinline__ float fma16(const float4* wr, const float4* __restrict__ sv,
                                       int lane) {
    float a0 = 0.f, a1 = 0.f, a2 = 0.f, a3 = 0.f;
#pragma unroll
    for (int j = 0; j < 16; j++) {
        float4 v = sv[lane + 32 * j];
        a0 += wr[j].x * v.x;
        a1 += wr[j].y * v.y;
        a2 += wr[j].z * v.z;
        a3 += wr[j].w * v.w;
    }
    return (a0 + a1) + (a2 + a3);
}

// ---------------------------------------------------------------------------
// K1: attn scores. warp-per-row (row = 1024 float4), 64 blocks.
__global__ void __launch_bounds__(256, 3)
k_attn_scores(const int* __restrict__ token, const float* __restrict__ hidden,
              const float* __restrict__ embedding,
              const float* __restrict__ attn_W, const float* __restrict__ attn_b) {
    __shared__ float4 sv[1024];
    int tid = threadIdx.x, lane = tid & 31, warp = tid >> 5;
    const float4* emb4 = (const float4*)(embedding + (size_t)__ldg(token) * H);
    const float4* hid4 = (const float4*)hidden;
#pragma unroll
    for (int k = 0; k < 2; k++) {
        int i = tid + 256 * k;
        sv[i] = __ldg(&emb4[i]);
        sv[i + 512] = __ldg(&hid4[i]);
    }
    __syncthreads();
    int row = blockIdx.x * 8 + warp;
    const float4* w4 = (const float4*)(attn_W + (size_t)row * 2 * H);
    float a = warpRowDot<4>(w4, sv, lane);
    if (lane == 0) g_scores[row] = a + __ldg(&attn_b[row]);
}

// ---------------------------------------------------------------------------
// K2: fused softmax + split-K context + last-block reduce (64 blocks).
__global__ void k_context(const float* __restrict__ enc,
                          float* __restrict__ out_aw) {
    __shared__ float s_e[L];
    __shared__ float sred[16];
    int tid = threadIdx.x, lane = tid & 31, warp = tid >> 5;
    float v0 = g_scores[tid], v1 = g_scores[tid + 256];
    float m = fmaxf(v0, v1);
#pragma unroll
    for (int o = 16; o; o >>= 1) m = fmaxf(m, __shfl_down_sync(0xffffffffu, m, o));
    if (lane == 0) sred[warp] = m;
    __syncthreads();
    if (warp == 0) {
        m = (lane < 8) ? sred[lane] : -1e30f;
#pragma unroll
        for (int o = 4; o; o >>= 1) m = fmaxf(m, __shfl_down_sync(0xffffffffu, m, o));
        if (lane == 0) sred[8] = m;
    }
    __syncthreads();
    m = sred[8];
    float e0 = expf(v0 - m), e1 = expf(v1 - m);
    s_e[tid] = e0;
    s_e[tid + 256] = e1;
    float sum = warpSum(e0 + e1);
    if (lane == 0) sred[warp] = sum;
    __syncthreads();
    if (warp == 0) {
        sum = (lane < 8) ? sred[lane] : 0.f;
        sum = warpSum(sum);
        if (lane == 0) sred[9] = sum;
    }
    __syncthreads();
    float inv = 1.f / sred[9];
    if (blockIdx.x == 0) {
        out_aw[tid] = s_e[tid] * inv;
        out_aw[tid + 256] = s_e[tid + 256] * inv;
    }
    int bx = blockIdx.x & 7, by = blockIdx.x >> 3;
    int r0 = by * 64;
    int col = bx * 256 + tid;
    float a0 = 0.f, a1 = 0.f, a2 = 0.f, a3 = 0.f;
#pragma unroll 4
    for (int l = 0; l < 64; l += 4) {
        a0 += s_e[r0 + l + 0] * __ldcs(&enc[(size_t)(r0 + l + 0) * H + col]);
        a1 += s_e[r0 + l + 1] * __ldcs(&enc[(size_t)(r0 + l + 1) * H + col]);
        a2 += s_e[r0 + l + 2] * __ldcs(&enc[(size_t)(r0 + l + 2) * H + col]);
        a3 += s_e[r0 + l + 3] * __ldcs(&enc[(size_t)(r0 + l + 3) * H + col]);
    }
    g_ctx_part[by * H + col] = ((a0 + a1) + (a2 + a3)) * inv;

    __threadfence();
    __shared__ bool isLast;
    if (tid == 0) isLast = (atomicAdd(&g_cnt_ctx, 1) == 63);
    __syncthreads();
    if (isLast) {
        const float4* p4 = (const float4*)g_ctx_part;
#pragma unroll
        for (int k = 0; k < 2; k++) {
            int i = tid + 256 * k;
            float4 c = p4[i];
#pragma unroll
            for (int p = 1; p < 8; p++) {
                float4 q = p4[p * (H / 4) + i];
                c.x += q.x; c.y += q.y; c.z += q.z; c.w += q.w;
            }
            ((float4*)g_ctx)[i] = c;
        }
        if (tid == 0) g_cnt_ctx = 0;
    }
}

// ---------------------------------------------------------------------------
// K3: combine. warp-per-row (row = 1024 float4), 256 blocks.
__global__ void __launch_bounds__(256, 3)
k_combine(const int* __restrict__ token, const float* __restrict__ embedding,
          const float* __restrict__ comb_W, const float* __restrict__ comb_b) {
    __shared__ float4 sv[1024];
    int tid = threadIdx.x, lane = tid & 31, warp = tid >> 5;
    const float4* emb4 = (const float4*)(embedding + (size_t)__ldg(token) * H);
    const float4* ctx4 = (const float4*)g_ctx;
#pragma unroll
    for (int k = 0; k < 2; k++) {
        int i = tid + 256 * k;
        sv[i] = __ldg(&emb4[i]);
        sv[i + 512] = __ldg(&ctx4[i]);
    }
    __syncthreads();
    int row = blockIdx.x * 8 + warp;
    const float4* w4 = (const float4*)(comb_W + (size_t)row * 2 * H);
    float a = warpRowDot<4>(w4, sv, lane);
    if (lane == 0) g_x[row] = fmaxf(a + __ldg(&comb_b[row]), 0.f);
}

// ---------------------------------------------------------------------------
// K4: GRU gates (ih + hh, 100 MB). 444 blocks, static stride loop, full-row
// 16-batch + cross-row prefetch issued before the reduce. No atomics/syncs.
__global__ void __launch_bounds__(256, 3)
k_gates(const float* __restrict__ w_ih, const float* __restrict__ w_hh,
        const float* __restrict__ b_ih, const float* __restrict__ b_hh,
        const float* __restrict__ hidden) {
    __shared__ float4 sv[1024];   // [0:512)=x, [512:1024)=hidden
    int tid = threadIdx.x, lane = tid & 31, warp = tid >> 5;
    const float4* x4 = (const float4*)g_x;
    const float4* h4 = (const float4*)hidden;
#pragma unroll
    for (int k = 0; k < 2; k++) {
        int i = tid + 256 * k;
        sv[i] = __ldg(&x4[i]);
        sv[i + 512] = __ldg(&h4[i]);
    }
    __syncthreads();
    const int stride = NB_GATES * 8;  // 3552
    int row = blockIdx.x * 8 + warp;
    if (row >= 6 * H) return;
    float4 A[16];
    {
        bool ih = row < 3 * H;
        const float4* wp = ih ? (const float4*)(w_ih + (size_t)row * H)
                              : (const float4*)(w_hh + (size_t)(row - 3 * H) * H);
        load16(A, wp, lane);
    }
    while (true) {
        int nrow = row + stride;
        int prow = (nrow < 6 * H) ? nrow : row;   // clamp last prefetch
        bool ihp = prow < 3 * H;
        const float4* wpn = ihp ? (const float4*)(w_ih + (size_t)prow * H)
                                : (const float4*)(w_hh + (size_t)(prow - 3 * H) * H);
        bool ih = row < 3 * H;
        float acc = fma16(A, ih ? sv : sv + 512, lane);
        load16(A, wpn, lane);                     // in flight during reduce
        float a = warpSum(acc);
        if (lane == 0) {
            int lrow = ih ? row : row - 3 * H;
            g_gates[row] = a + __ldg(ih ? &b_ih[lrow] : &b_hh[lrow]);
        }
        if (nrow >= 6 * H) break;
        row = nrow;
    }
}

// ---------------------------------------------------------------------------
// K5: logits GEMV (412 MB), persistent, h_new computed in every block's
// prologue (deterministic, redundant, L2-resident). Block 0 writes out_h.
__global__ void __launch_bounds__(256, 3)
k_logits(const float* __restrict__ out_W, const float* __restrict__ out_b,
         const float* __restrict__ hidden, float* __restrict__ out,
         float* __restrict__ out_h) {
    __shared__ float4 sv[512];
    __shared__ float smm[8], sss[8];
    int tid = threadIdx.x, lane = tid & 31, warp = tid >> 5;
    float* svf = (float*)sv;
    const float* gi = g_gates;
    const float* gh = g_gates + 3 * H;
#pragma unroll
    for (int k = 0; k < 8; k++) {
        int i = tid + 256 * k;   // 0..2047
        float r = 1.f / (1.f + expf(-(gi[i] + gh[i])));
        float z = 1.f / (1.f + expf(-(gi[H + i] + gh[H + i])));
        float n = tanhf(gi[2 * H + i] + r * gh[2 * H + i]);
        float hn = (1.f - z) * n + z * hidden[i];
        svf[i] = hn;
        if (blockIdx.x == 0) out_h[i] = hn;
    }
    __syncthreads();
    const int stride = NB_LOGITS * 8;  // 3552
    int row = blockIdx.x * 8 + warp;
    float pm = -1e30f, ps = 0.f;
    if (row < V) {
        float4 A[16];
        const float4* wp = (const float4*)(out_W + (size_t)row * H);
        load16(A, wp, lane);
        while (true) {
            int nrow = row + stride;
            int prow = (nrow < V) ? nrow : row;   // clamp last prefetch
            const float4* wpn = (const float4*)(out_W + (size_t)prow * H);
            float acc = fma16(A, sv, lane);
            load16(A, wpn, lane);                 // next row, before reduce
            float a = warpSum(acc);
            if (lane == 0) {
                float val = a + __ldg(&out_b[row]);
                out[row] = val;
                float M = fmaxf(pm, val);
                ps = ps * expf(pm - M) + expf(val - M);
                pm = M;
            }
            if (nrow >= V) break;
            row = nrow;
        }
    }
    if (lane == 0) { smm[warp] = pm; sss[warp] = ps; }
    __syncthreads();
    if (tid == 0) {
        float m = smm[0], s = sss[0];
#pragma unroll
        for (int k = 1; k < 8; k++) {
            float M = fmaxf(m, smm[k]);
            s = s * expf(m - M) + sss[k] * expf(smm[k] - M);
            m = M;
        }
        g_lmax[blockIdx.x] = m;
        g_lsum[blockIdx.x] = s;
    }
}

// ---------------------------------------------------------------------------
// K6: every block merges the 444 (max,sum) partials locally (fixed order),
// then subtracts lse from its slice of logits.
__global__ void k_logsoftmax(float* __restrict__ out) {
    __shared__ float smm[8], sss[8];
    __shared__ float s_lse;
    int tid = threadIdx.x, lane = tid & 31, warp = tid >> 5;
    float m = -1e30f, s = 0.f;
    for (int i = tid; i < NB_LOGITS; i += 256) {
        float m2 = g_lmax[i], s2 = g_lsum[i];
        float M = fmaxf(m, m2);
        s = s * expf(m - M) + s2 * expf(m2 - M);
        m = M;
    }
#pragma unroll
    for (int o = 16; o; o >>= 1) {
        float m2 = __shfl_down_sync(0xffffffffu, m, o);
        float s2 = __shfl_down_sync(0xffffffffu, s, o);
        float M = fmaxf(m, m2);
        s = s * expf(m - M) + s2 * expf(m2 - M);
        m = M;
    }
    if (lane == 0) { smm[warp] = m; sss[warp] = s; }
    __syncthreads();
    if (tid == 0) {
        m = smm[0]; s = sss[0];
#pragma unroll
        for (int k = 1; k < 8; k++) {
            float M = fmaxf(m, smm[k]);
            s = s * expf(m - M) + sss[k] * expf(smm[k] - M);
            m = M;
        }
        s_lse = m + logf(s);
    }
    __syncthreads();
    int i = blockIdx.x * 256 + tid;
    if (i < V) out[i] -= s_lse;
}

extern "C" void kernel_launch(void* const* d_in, const int* in_sizes, int n_in,
                              void* d_out, int out_size) {
    const int*   token     = (const int*)d_in[0];
    const float* hidden    = (const float*)d_in[1];
    const float* enc       = (const float*)d_in[2];
    const float* embedding = (const float*)d_in[3];
    const float* attn_W    = (const float*)d_in[4];
    const float* attn_b    = (const float*)d_in[5];
    const float* comb_W    = (const float*)d_in[6];
    const float* comb_b    = (const float*)d_in[7];
    const float* w_ih      = (const float*)d_in[8];
    const float* w_hh      = (const float*)d_in[9];
    const float* b_ih      = (const float*)d_in[10];
    const float* b_hh      = (const float*)d_in[11];
    const float* out_W     = (const float*)d_in[12];
    const float* out_b     = (const float*)d_in[13];

    float* out = (float*)d_out;
    float* out_logits = out;
    float* out_h      = out + V;
    float* out_aw     = out + V + H;

    k_attn_scores<<<L / 8, 256>>>(token, hidden, embedding, attn_W, attn_b);
    k_context<<<64, 256>>>(enc, out_aw);
    k_combine<<<H / 8, 256>>>(token, embedding, comb_W, comb_b);
    k_gates<<<NB_GATES, 256>>>(w_ih, w_hh, b_ih, b_hh, hidden);
    k_logits<<<NB_LOGITS, 256>>>(out_W, out_b, hidden, out_logits, out_h);
    k_logsoftmax<<<(V + 255) / 256, 256>>>(out_logits);
}

// round 11
// speedup vs baseline: 1.0770x; 1.0770x over previous
#include <cuda_runtime.h>
#include <math.h>

// ---------------- scratch (device globals; no allocation allowed) ----------
__device__ float g_scores[512];         // attn logits
__device__ float g_ctx_part[8 * 2048];  // split-K context partials
__device__ float g_ctx[2048];           // reduced context
__device__ float g_x[2048];             // relu(attn_combine)
__device__ float g_gates[12288];        // gi[0:6144), gh[6144:12288)
__device__ float g_hnew[2048];          // new hidden
__device__ float g_lmax[512];           // per-block logits max partials
__device__ float g_lsum[512];           // per-block sumexp partials
__device__ int   g_cnt_ctx;             // ctx arrival counter (self-resetting)

#define H 2048
#define V 50257
#define L 512
#define NB_LOGITS 444
#define NB_GATES 444

__device__ __forceinline__ float warpSum(float v) {
#pragma unroll
    for (int o = 16; o; o >>= 1) v += __shfl_down_sync(0xffffffffu, v, o);
    return v;
}

// ---- 8-float4 chunk helpers (A/B pipelined dot) ----
__device__ __forceinline__ void loadChunk(float4* dst, const float4* __restrict__ w4,
                                          int lane) {
#pragma unroll
    for (int j = 0; j < 8; j++) dst[j] = __ldcs(&w4[lane + 32 * j]);
}
__device__ __forceinline__ float dotChunk(const float4* wr, const float4* __restrict__ sv,
                                          int lane) {
    float a0 = 0.f, a1 = 0.f, a2 = 0.f, a3 = 0.f;
#pragma unroll
    for (int j = 0; j < 8; j++) {
        float4 v = sv[lane + 32 * j];
        a0 += wr[j].x * v.x;
        a1 += wr[j].y * v.y;
        a2 += wr[j].z * v.z;
        a3 += wr[j].w * v.w;
    }
    return (a0 + a1) + (a2 + a3);
}
template <int NC>
__device__ __forceinline__ float warpRowDot(const float4* __restrict__ w4,
                                            const float4* __restrict__ sv,
                                            int lane) {
    float4 A[8], B[8];
    loadChunk(A, w4, lane);
    float acc = 0.f;
#pragma unroll
    for (int c = 0; c < NC; c++) {
        float4* cur = (c & 1) ? B : A;
        float4* nxt = (c & 1) ? A : B;
        if (c + 1 < NC) loadChunk(nxt, w4 + (c + 1) * 256, lane);
        acc += dotChunk(cur, sv + c * 256, lane);
    }
    return warpSum(acc);
}

// ---- 16-float4 front-batched dot (R5's measured-best gates shape) ----
__device__ __forceinline__ float warpDot512(const float4* __restrict__ w4,
                                            const float4* __restrict__ sv,
                                            int lane) {
    float4 wr[16];
#pragma unroll
    for (int j = 0; j < 16; j++) wr[j] = __ldcs(&w4[lane + 32 * j]);
    float a0 = 0.f, a1 = 0.f, a2 = 0.f, a3 = 0.f;
#pragma unroll
    for (int j = 0; j < 16; j++) {
        float4 v = sv[lane + 32 * j];
        a0 += wr[j].x * v.x;
        a1 += wr[j].y * v.y;
        a2 += wr[j].z * v.z;
        a3 += wr[j].w * v.w;
    }
    return warpSum((a0 + a1) + (a2 + a3));
}

// ---------------------------------------------------------------------------
// K1: attn scores. warp-per-row (row = 1024 float4), 64 blocks.
__global__ void __launch_bounds__(256, 3)
k_attn_scores(const int* __restrict__ token, const float* __restrict__ hidden,
              const float* __restrict__ embedding,
              const float* __restrict__ attn_W, const float* __restrict__ attn_b) {
    __shared__ float4 sv[1024];
    int tid = threadIdx.x, lane = tid & 31, warp = tid >> 5;
    const float4* emb4 = (const float4*)(embedding + (size_t)__ldg(token) * H);
    const float4* hid4 = (const float4*)hidden;
#pragma unroll
    for (int k = 0; k < 2; k++) {
        int i = tid + 256 * k;
        sv[i] = __ldg(&emb4[i]);
        sv[i + 512] = __ldg(&hid4[i]);
    }
    __syncthreads();
    int row = blockIdx.x * 8 + warp;
    const float4* w4 = (const float4*)(attn_W + (size_t)row * 2 * H);
    float a = warpRowDot<4>(w4, sv, lane);
    if (lane == 0) g_scores[row] = a + __ldg(&attn_b[row]);
}

// ---------------------------------------------------------------------------
// K2: fused softmax + split-K context + last-block reduce (64 blocks).
__global__ void k_context(const float* __restrict__ enc,
                          float* __restrict__ out_aw) {
    __shared__ float s_e[L];
    __shared__ float sred[16];
    int tid = threadIdx.x, lane = tid & 31, warp = tid >> 5;
    float v0 = g_scores[tid], v1 = g_scores[tid + 256];
    float m = fmaxf(v0, v1);
#pragma unroll
    for (int o = 16; o; o >>= 1) m = fmaxf(m, __shfl_down_sync(0xffffffffu, m, o));
    if (lane == 0) sred[warp] = m;
    __syncthreads();
    if (warp == 0) {
        m = (lane < 8) ? sred[lane] : -1e30f;
#pragma unroll
        for (int o = 4; o; o >>= 1) m = fmaxf(m, __shfl_down_sync(0xffffffffu, m, o));
        if (lane == 0) sred[8] = m;
    }
    __syncthreads();
    m = sred[8];
    float e0 = expf(v0 - m), e1 = expf(v1 - m);
    s_e[tid] = e0;
    s_e[tid + 256] = e1;
    float sum = warpSum(e0 + e1);
    if (lane == 0) sred[warp] = sum;
    __syncthreads();
    if (warp == 0) {
        sum = (lane < 8) ? sred[lane] : 0.f;
        sum = warpSum(sum);
        if (lane == 0) sred[9] = sum;
    }
    __syncthreads();
    float inv = 1.f / sred[9];
    if (blockIdx.x == 0) {
        out_aw[tid] = s_e[tid] * inv;
        out_aw[tid + 256] = s_e[tid + 256] * inv;
    }
    int bx = blockIdx.x & 7, by = blockIdx.x >> 3;
    int r0 = by * 64;
    int col = bx * 256 + tid;
    float a0 = 0.f, a1 = 0.f, a2 = 0.f, a3 = 0.f;
#pragma unroll 4
    for (int l = 0; l < 64; l += 4) {
        a0 += s_e[r0 + l + 0] * __ldcs(&enc[(size_t)(r0 + l + 0) * H + col]);
        a1 += s_e[r0 + l + 1] * __ldcs(&enc[(size_t)(r0 + l + 1) * H + col]);
        a2 += s_e[r0 + l + 2] * __ldcs(&enc[(size_t)(r0 + l + 2) * H + col]);
        a3 += s_e[r0 + l + 3] * __ldcs(&enc[(size_t)(r0 + l + 3) * H + col]);
    }
    g_ctx_part[by * H + col] = ((a0 + a1) + (a2 + a3)) * inv;

    __threadfence();
    __shared__ bool isLast;
    if (tid == 0) isLast = (atomicAdd(&g_cnt_ctx, 1) == 63);
    __syncthreads();
    if (isLast) {
        const float4* p4 = (const float4*)g_ctx_part;
#pragma unroll
        for (int k = 0; k < 2; k++) {
            int i = tid + 256 * k;
            float4 c = p4[i];
#pragma unroll
            for (int p = 1; p < 8; p++) {
                float4 q = p4[p * (H / 4) + i];
                c.x += q.x; c.y += q.y; c.z += q.z; c.w += q.w;
            }
            ((float4*)g_ctx)[i] = c;
        }
        if (tid == 0) g_cnt_ctx = 0;
    }
}

// ---------------------------------------------------------------------------
// K3: combine. warp-per-row (row = 1024 float4), 256 blocks.
__global__ void __launch_bounds__(256, 3)
k_combine(const int* __restrict__ token, const float* __restrict__ embedding,
          const float* __restrict__ comb_W, const float* __restrict__ comb_b) {
    __shared__ float4 sv[1024];
    int tid = threadIdx.x, lane = tid & 31, warp = tid >> 5;
    const float4* emb4 = (const float4*)(embedding + (size_t)__ldg(token) * H);
    const float4* ctx4 = (const float4*)g_ctx;
#pragma unroll
    for (int k = 0; k < 2; k++) {
        int i = tid + 256 * k;
        sv[i] = __ldg(&emb4[i]);
        sv[i + 512] = __ldg(&ctx4[i]);
    }
    __syncthreads();
    int row = blockIdx.x * 8 + warp;
    const float4* w4 = (const float4*)(comb_W + (size_t)row * 2 * H);
    float a = warpRowDot<4>(w4, sv, lane);
    if (lane == 0) g_x[row] = fmaxf(a + __ldg(&comb_b[row]), 0.f);
}

// ---------------------------------------------------------------------------
// K4: GRU gates (ih + hh, 100 MB). R5's measured-best shape: 444 blocks,
// static stride loop, 16-deep front-batched warpDot512, no cross prefetch.
__global__ void __launch_bounds__(256, 3)
k_gates(const float* __restrict__ w_ih, const float* __restrict__ w_hh,
        const float* __restrict__ b_ih, const float* __restrict__ b_hh,
        const float* __restrict__ hidden) {
    __shared__ float4 sv[1024];   // [0:512)=x, [512:1024)=hidden
    int tid = threadIdx.x, lane = tid & 31, warp = tid >> 5;
    const float4* x4 = (const float4*)g_x;
    const float4* h4 = (const float4*)hidden;
#pragma unroll
    for (int k = 0; k < 2; k++) {
        int i = tid + 256 * k;
        sv[i] = __ldg(&x4[i]);
        sv[i + 512] = __ldg(&h4[i]);
    }
    __syncthreads();
    for (int row = blockIdx.x * 8 + warp; row < 6 * H; row += NB_GATES * 8) {
        bool ih = row < 3 * H;
        int lrow = ih ? row : row - 3 * H;
        const float* W = ih ? w_ih : w_hh;
        const float4* w4 = (const float4*)(W + (size_t)lrow * H);
        float a = warpDot512(w4, ih ? sv : sv + 512, lane);
        if (lane == 0)
            g_gates[row] = a + __ldg(ih ? &b_ih[lrow] : &b_hh[lrow]);
    }
}

// ---------------------------------------------------------------------------
// K5: GRU gate combine -> h_new
__global__ void k_hnew(const float* __restrict__ hidden, float* __restrict__ out_h) {
    int i = blockIdx.x * blockDim.x + threadIdx.x;
    if (i >= H) return;
    const float* gi = g_gates;
    const float* gh = g_gates + 3 * H;
    float r = 1.f / (1.f + expf(-(gi[i] + gh[i])));
    float z = 1.f / (1.f + expf(-(gi[H + i] + gh[H + i])));
    float n = tanhf(gi[2 * H + i] + r * gh[2 * H + i]);
    float hn = (1.f - z) * n + z * hidden[i];
    g_hnew[i] = hn;
    out_h[i] = hn;
}

// ---------------------------------------------------------------------------
// K6: logits GEMV (412 MB). R6-proposal's measured-best shape: persistent
// 444 blocks, 8+8 A/B chunk pipeline + cross-row prefetch, running lse
// partials in lane 0, per-block partial via plain stores.
__global__ void __launch_bounds__(256, 3)
k_logits(const float* __restrict__ out_W, const float* __restrict__ out_b,
         float* __restrict__ out) {
    __shared__ float4 sv[512];
    __shared__ float smm[8], sss[8];
    int tid = threadIdx.x, lane = tid & 31, warp = tid >> 5;
    const float4* v4 = (const float4*)g_hnew;
#pragma unroll
    for (int k = 0; k < 2; k++) sv[tid + 256 * k] = __ldg(&v4[tid + 256 * k]);
    __syncthreads();
    const int stride = NB_LOGITS * 8;  // 3552
    int row = blockIdx.x * 8 + warp;
    float pm = -1e30f, ps = 0.f;
    if (row < V) {
        float4 A[8], B[8];
        const float4* wp = (const float4*)(out_W + (size_t)row * H);
        loadChunk(A, wp, lane);
        while (true) {
            int nrow = row + stride;
            int prow = (nrow < V) ? nrow : row;  // clamp last prefetch
            const float4* wpn = (const float4*)(out_W + (size_t)prow * H);
            loadChunk(B, wp + 256, lane);
            float acc = dotChunk(A, sv, lane);
            loadChunk(A, wpn, lane);
            acc += dotChunk(B, sv + 256, lane);
            float a = warpSum(acc);
            if (lane == 0) {
                float val = a + __ldg(&out_b[row]);
                out[row] = val;
                float M = fmaxf(pm, val);
                ps = ps * expf(pm - M) + expf(val - M);
                pm = M;
            }
            if (nrow >= V) break;
            row = nrow;
            wp = wpn;
        }
    }
    if (lane == 0) { smm[warp] = pm; sss[warp] = ps; }
    __syncthreads();
    if (tid == 0) {
        float m = smm[0], s = sss[0];
#pragma unroll
        for (int k = 1; k < 8; k++) {
            float M = fmaxf(m, smm[k]);
            s = s * expf(m - M) + sss[k] * expf(smm[k] - M);
            m = M;
        }
        g_lmax[blockIdx.x] = m;
        g_lsum[blockIdx.x] = s;
    }
}

// ---------------------------------------------------------------------------
// K7: every block merges the 444 (max,sum) partials locally (fixed order),
// then subtracts lse from its slice of logits.
__global__ void k_logsoftmax(float* __restrict__ out) {
    __shared__ float smm[8], sss[8];
    __shared__ float s_lse;
    int tid = threadIdx.x, lane = tid & 31, warp = tid >> 5;
    float m = -1e30f, s = 0.f;
    for (int i = tid; i < NB_LOGITS; i += 256) {
        float m2 = g_lmax[i], s2 = g_lsum[i];
        float M = fmaxf(m, m2);
        s = s * expf(m - M) + s2 * expf(m2 - M);
        m = M;
    }
#pragma unroll
    for (int o = 16; o; o >>= 1) {
        float m2 = __shfl_down_sync(0xffffffffu, m, o);
        float s2 = __shfl_down_sync(0xffffffffu, s, o);
        float M = fmaxf(m, m2);
        s = s * expf(m - M) + s2 * expf(m2 - M);
        m = M;
    }
    if (lane == 0) { smm[warp] = m; sss[warp] = s; }
    __syncthreads();
    if (tid == 0) {
        m = smm[0]; s = sss[0];
#pragma unroll
        for (int k = 1; k < 8; k++) {
            float M = fmaxf(m, smm[k]);
            s = s * expf(m - M) + sss[k] * expf(smm[k] - M);
            m = M;
        }
        s_lse = m + logf(s);
    }
    __syncthreads();
    int i = blockIdx.x * 256 + tid;
    if (i < V) out[i] -= s_lse;
}

extern "C" void kernel_launch(void* const* d_in, const int* in_sizes, int n_in,
                              void* d_out, int out_size) {
    const int*   token     = (const int*)d_in[0];
    const float* hidden    = (const float*)d_in[1];
    const float* enc       = (const float*)d_in[2];
    const float* embedding = (const float*)d_in[3];
    const float* attn_W    = (const float*)d_in[4];
    const float* attn_b    = (const float*)d_in[5];
    const float* comb_W    = (const float*)d_in[6];
    const float* comb_b    = (const float*)d_in[7];
    const float* w_ih      = (const float*)d_in[8];
    const float* w_hh      = (const float*)d_in[9];
    const float* b_ih      = (const float*)d_in[10];
    const float* b_hh      = (const float*)d_in[11];
    const float* out_W     = (const float*)d_in[12];
    const float* out_b     = (const float*)d_in[13];

    float* out = (float*)d_out;
    float* out_logits = out;
    float* out_h      = out + V;
    float* out_aw     = out + V + H;

    k_attn_scores<<<L / 8, 256>>>(token, hidden, embedding, attn_W, attn_b);
    k_context<<<64, 256>>>(enc, out_aw);
    k_combine<<<H / 8, 256>>>(token, embedding, comb_W, comb_b);
    k_gates<<<NB_GATES, 256>>>(w_ih, w_hh, b_ih, b_hh, hidden);
    k_hnew<<<H / 256, 256>>>(hidden, out_h);
    k_logits<<<NB_LOGITS, 256>>>(out_W, out_b, out_logits);
    k_logsoftmax<<<(V + 255) / 256, 256>>>(out_logits);
}

// round 12
// speedup vs baseline: 1.0789x; 1.0018x over previous
#include <cuda_runtime.h>
#include <math.h>

// ---------------- scratch (device globals; no allocation allowed) ----------
__device__ float g_scores[512];         // attn logits
__device__ float g_ctx_part[8 * 2048];  // split-K context partials
__device__ float g_ctx[2048];           // reduced context
__device__ float g_x[2048];             // relu(attn_combine)
__device__ float g_gates[12288];        // gi[0:6144), gh[6144:12288)
__device__ float g_hnew[2048];          // new hidden
__device__ float g_lmax[512];           // per-block logits max partials
__device__ float g_lsum[512];           // per-block sumexp partials
__device__ int   g_cnt_ctx;             // ctx arrival counter (self-resetting)

#define H 2048
#define V 50257
#define L 512
#define NB_LOGITS 444
#define NB_GATES 444

__device__ __forceinline__ float warpSum(float v) {
#pragma unroll
    for (int o = 16; o; o >>= 1) v += __shfl_down_sync(0xffffffffu, v, o);
    return v;
}

// ---- 8-float4 chunk helpers (A/B pipelined dot) ----
__device__ __forceinline__ void loadChunk(float4* dst, const float4* __restrict__ w4,
                                          int lane) {
#pragma unroll
    for (int j = 0; j < 8; j++) dst[j] = __ldcs(&w4[lane + 32 * j]);
}
__device__ __forceinline__ float dotChunk(const float4* wr, const float4* __restrict__ sv,
                                          int lane) {
    float a0 = 0.f, a1 = 0.f, a2 = 0.f, a3 = 0.f;
#pragma unroll
    for (int j = 0; j < 8; j++) {
        float4 v = sv[lane + 32 * j];
        a0 += wr[j].x * v.x;
        a1 += wr[j].y * v.y;
        a2 += wr[j].z * v.z;
        a3 += wr[j].w * v.w;
    }
    return (a0 + a1) + (a2 + a3);
}
template <int NC>
__device__ __forceinline__ float warpRowDot(const float4* __restrict__ w4,
                                            const float4* __restrict__ sv,
                                            int lane) {
    float4 A[8], B[8];
    loadChunk(A, w4, lane);
    float acc = 0.f;
#pragma unroll
    for (int c = 0; c < NC; c++) {
        float4* cur = (c & 1) ? B : A;
        float4* nxt = (c & 1) ? A : B;
        if (c + 1 < NC) loadChunk(nxt, w4 + (c + 1) * 256, lane);
        acc += dotChunk(cur, sv + c * 256, lane);
    }
    return warpSum(acc);
}

// ---------------------------------------------------------------------------
// K1: attn scores. warp-per-row (row = 1024 float4), 64 blocks.
__global__ void __launch_bounds__(256, 3)
k_attn_scores(const int* __restrict__ token, const float* __restrict__ hidden,
              const float* __restrict__ embedding,
              const float* __restrict__ attn_W, const float* __restrict__ attn_b) {
    __shared__ float4 sv[1024];
    int tid = threadIdx.x, lane = tid & 31, warp = tid >> 5;
    const float4* emb4 = (const float4*)(embedding + (size_t)__ldg(token) * H);
    const float4* hid4 = (const float4*)hidden;
#pragma unroll
    for (int k = 0; k < 2; k++) {
        int i = tid + 256 * k;
        sv[i] = __ldg(&emb4[i]);
        sv[i + 512] = __ldg(&hid4[i]);
    }
    __syncthreads();
    int row = blockIdx.x * 8 + warp;
    const float4* w4 = (const float4*)(attn_W + (size_t)row * 2 * H);
    float a = warpRowDot<4>(w4, sv, lane);
    if (lane == 0) g_scores[row] = a + __ldg(&attn_b[row]);
}

// ---------------------------------------------------------------------------
// K2: fused softmax + split-K context + last-block reduce (64 blocks).
__global__ void k_context(const float* __restrict__ enc,
                          float* __restrict__ out_aw) {
    __shared__ float s_e[L];
    __shared__ float sred[16];
    int tid = threadIdx.x, lane = tid & 31, warp = tid >> 5;
    float v0 = g_scores[tid], v1 = g_scores[tid + 256];
    float m = fmaxf(v0, v1);
#pragma unroll
    for (int o = 16; o; o >>= 1) m = fmaxf(m, __shfl_down_sync(0xffffffffu, m, o));
    if (lane == 0) sred[warp] = m;
    __syncthreads();
    if (warp == 0) {
        m = (lane < 8) ? sred[lane] : -1e30f;
#pragma unroll
        for (int o = 4; o; o >>= 1) m = fmaxf(m, __shfl_down_sync(0xffffffffu, m, o));
        if (lane == 0) sred[8] = m;
    }
    __syncthreads();
    m = sred[8];
    float e0 = expf(v0 - m), e1 = expf(v1 - m);
    s_e[tid] = e0;
    s_e[tid + 256] = e1;
    float sum = warpSum(e0 + e1);
    if (lane == 0) sred[warp] = sum;
    __syncthreads();
    if (warp == 0) {
        sum = (lane < 8) ? sred[lane] : 0.f;
        sum = warpSum(sum);
        if (lane == 0) sred[9] = sum;
    }
    __syncthreads();
    float inv = 1.f / sred[9];
    if (blockIdx.x == 0) {
        out_aw[tid] = s_e[tid] * inv;
        out_aw[tid + 256] = s_e[tid + 256] * inv;
    }
    int bx = blockIdx.x & 7, by = blockIdx.x >> 3;
    int r0 = by * 64;
    int col = bx * 256 + tid;
    float a0 = 0.f, a1 = 0.f, a2 = 0.f, a3 = 0.f;
#pragma unroll 4
    for (int l = 0; l < 64; l += 4) {
        a0 += s_e[r0 + l + 0] * __ldcs(&enc[(size_t)(r0 + l + 0) * H + col]);
        a1 += s_e[r0 + l + 1] * __ldcs(&enc[(size_t)(r0 + l + 1) * H + col]);
        a2 += s_e[r0 + l + 2] * __ldcs(&enc[(size_t)(r0 + l + 2) * H + col]);
        a3 += s_e[r0 + l + 3] * __ldcs(&enc[(size_t)(r0 + l + 3) * H + col]);
    }
    g_ctx_part[by * H + col] = ((a0 + a1) + (a2 + a3)) * inv;

    __threadfence();
    __shared__ bool isLast;
    if (tid == 0) isLast = (atomicAdd(&g_cnt_ctx, 1) == 63);
    __syncthreads();
    if (isLast) {
        const float4* p4 = (const float4*)g_ctx_part;
#pragma unroll
        for (int k = 0; k < 2; k++) {
            int i = tid + 256 * k;
            float4 c = p4[i];
#pragma unroll
            for (int p = 1; p < 8; p++) {
                float4 q = p4[p * (H / 4) + i];
                c.x += q.x; c.y += q.y; c.z += q.z; c.w += q.w;
            }
            ((float4*)g_ctx)[i] = c;
        }
        if (tid == 0) g_cnt_ctx = 0;
    }
}

// ---------------------------------------------------------------------------
// K3: combine. warp-per-row (row = 1024 float4), 256 blocks.
__global__ void __launch_bounds__(256, 3)
k_combine(const int* __restrict__ token, const float* __restrict__ embedding,
          const float* __restrict__ comb_W, const float* __restrict__ comb_b) {
    __shared__ float4 sv[1024];
    int tid = threadIdx.x, lane = tid & 31, warp = tid >> 5;
    const float4* emb4 = (const float4*)(embedding + (size_t)__ldg(token) * H);
    const float4* ctx4 = (const float4*)g_ctx;
#pragma unroll
    for (int k = 0; k < 2; k++) {
        int i = tid + 256 * k;
        sv[i] = __ldg(&emb4[i]);
        sv[i + 512] = __ldg(&ctx4[i]);
    }
    __syncthreads();
    int row = blockIdx.x * 8 + warp;
    const float4* w4 = (const float4*)(comb_W + (size_t)row * 2 * H);
    float a = warpRowDot<4>(w4, sv, lane);
    if (lane == 0) g_x[row] = fmaxf(a + __ldg(&comb_b[row]), 0.f);
}

// ---------------------------------------------------------------------------
// K4: GRU gates (ih + hh, 100 MB). Logits-style chunked A/B pipeline with
// cross-row prefetch, 444 balanced grid. Last prefetch clamps to ih row 0
// (L2-served, no redundant DRAM stream).
__device__ __forceinline__ const float4* gateRow(int r,
                                                 const float* __restrict__ w_ih,
                                                 const float* __restrict__ w_hh) {
    return (r < 3 * H) ? (const float4*)(w_ih + (size_t)r * H)
                       : (const float4*)(w_hh + (size_t)(r - 3 * H) * H);
}

__global__ void __launch_bounds__(256, 3)
k_gates(const float* __restrict__ w_ih, const float* __restrict__ w_hh,
        const float* __restrict__ b_ih, const float* __restrict__ b_hh,
        const float* __restrict__ hidden) {
    __shared__ float4 sv[1024];   // [0:512)=x, [512:1024)=hidden
    int tid = threadIdx.x, lane = tid & 31, warp = tid >> 5;
    const float4* x4 = (const float4*)g_x;
    const float4* h4 = (const float4*)hidden;
#pragma unroll
    for (int k = 0; k < 2; k++) {
        int i = tid + 256 * k;
        sv[i] = __ldg(&x4[i]);
        sv[i + 512] = __ldg(&h4[i]);
    }
    __syncthreads();
    const int stride = NB_GATES * 8;  // 3552
    int row = blockIdx.x * 8 + warp;
    float4 A[8], B[8];
    const float4* wp = gateRow(row, w_ih, w_hh);
    loadChunk(A, wp, lane);
    while (true) {
        int nrow = row + stride;
        // clamp last prefetch to ih row 0 (shared by all warps -> L2 hit)
        const float4* wpn = (nrow < 6 * H) ? gateRow(nrow, w_ih, w_hh)
                                           : (const float4*)w_ih;
        const float4* svb = (row < 3 * H) ? sv : sv + 512;
        loadChunk(B, wp + 256, lane);
        float acc = dotChunk(A, svb, lane);
        loadChunk(A, wpn, lane);                // in flight during reduce
        acc += dotChunk(B, svb + 256, lane);
        float a = warpSum(acc);
        if (lane == 0) {
            bool ih = row < 3 * H;
            int lrow = ih ? row : row - 3 * H;
            g_gates[row] = a + __ldg(ih ? &b_ih[lrow] : &b_hh[lrow]);
        }
        if (nrow >= 6 * H) break;
        row = nrow;
        wp = wpn;
    }
}

// ---------------------------------------------------------------------------
// K5: GRU gate combine -> h_new
__global__ void k_hnew(const float* __restrict__ hidden, float* __restrict__ out_h) {
    int i = blockIdx.x * blockDim.x + threadIdx.x;
    if (i >= H) return;
    const float* gi = g_gates;
    const float* gh = g_gates + 3 * H;
    float r = 1.f / (1.f + expf(-(gi[i] + gh[i])));
    float z = 1.f / (1.f + expf(-(gi[H + i] + gh[H + i])));
    float n = tanhf(gi[2 * H + i] + r * gh[2 * H + i]);
    float hn = (1.f - z) * n + z * hidden[i];
    g_hnew[i] = hn;
    out_h[i] = hn;
}

// ---------------------------------------------------------------------------
// K6: logits GEMV (412 MB). Persistent 444 blocks, chunked A/B pipeline +
// cross-row prefetch (clamped to row 0 on the last iteration), running lse
// partials in lane 0, per-block partial via plain stores.
__global__ void __launch_bounds__(256, 3)
k_logits(const float* __restrict__ out_W, const float* __restrict__ out_b,
         float* __restrict__ out) {
    __shared__ float4 sv[512];
    __shared__ float smm[8], sss[8];
    int tid = threadIdx.x, lane = tid & 31, warp = tid >> 5;
    const float4* v4 = (const float4*)g_hnew;
#pragma unroll
    for (int k = 0; k < 2; k++) sv[tid + 256 * k] = __ldg(&v4[tid + 256 * k]);
    __syncthreads();
    const int stride = NB_LOGITS * 8;  // 3552
    int row = blockIdx.x * 8 + warp;
    float pm = -1e30f, ps = 0.f;
    if (row < V) {
        float4 A[8], B[8];
        const float4* wp = (const float4*)(out_W + (size_t)row * H);
        loadChunk(A, wp, lane);
        while (true) {
            int nrow = row + stride;
            // clamp last prefetch to row 0 (shared by all warps -> L2 hit)
            const float4* wpn = (nrow < V) ? (const float4*)(out_W + (size_t)nrow * H)
                                           : (const float4*)out_W;
            loadChunk(B, wp + 256, lane);
            float acc = dotChunk(A, sv, lane);
            loadChunk(A, wpn, lane);
            acc += dotChunk(B, sv + 256, lane);
            float a = warpSum(acc);
            if (lane == 0) {
                float val = a + __ldg(&out_b[row]);
                out[row] = val;
                float M = fmaxf(pm, val);
                ps = ps * expf(pm - M) + expf(val - M);
                pm = M;
            }
            if (nrow >= V) break;
            row = nrow;
            wp = wpn;
        }
    }
    if (lane == 0) { smm[warp] = pm; sss[warp] = ps; }
    __syncthreads();
    if (tid == 0) {
        float m = smm[0], s = sss[0];
#pragma unroll
        for (int k = 1; k < 8; k++) {
            float M = fmaxf(m, smm[k]);
            s = s * expf(m - M) + sss[k] * expf(smm[k] - M);
            m = M;
        }
        g_lmax[blockIdx.x] = m;
        g_lsum[blockIdx.x] = s;
    }
}

// ---------------------------------------------------------------------------
// K7: every block merges the 444 (max,sum) partials locally (fixed order),
// then subtracts lse from its slice of logits.
__global__ void k_logsoftmax(float* __restrict__ out) {
    __shared__ float smm[8], sss[8];
    __shared__ float s_lse;
    int tid = threadIdx.x, lane = tid & 31, warp = tid >> 5;
    float m = -1e30f, s = 0.f;
    for (int i = tid; i < NB_LOGITS; i += 256) {
        float m2 = g_lmax[i], s2 = g_lsum[i];
        float M = fmaxf(m, m2);
        s = s * expf(m - M) + s2 * expf(m2 - M);
        m = M;
    }
#pragma unroll
    for (int o = 16; o; o >>= 1) {
        float m2 = __shfl_down_sync(0xffffffffu, m, o);
        float s2 = __shfl_down_sync(0xffffffffu, s, o);
        float M = fmaxf(m, m2);
        s = s * expf(m - M) + s2 * expf(m2 - M);
        m = M;
    }
    if (lane == 0) { smm[warp] = m; sss[warp] = s; }
    __syncthreads();
    if (tid == 0) {
        m = smm[0]; s = sss[0];
#pragma unroll
        for (int k = 1; k < 8; k++) {
            float M = fmaxf(m, smm[k]);
            s = s * expf(m - M) + sss[k] * expf(smm[k] - M);
            m = M;
        }
        s_lse = m + logf(s);
    }
    __syncthreads();
    int i = blockIdx.x * 256 + tid;
    if (i < V) out[i] -= s_lse;
}

extern "C" void kernel_launch(void* const* d_in, const int* in_sizes, int n_in,
                              void* d_out, int out_size) {
    const int*   token     = (const int*)d_in[0];
    const float* hidden    = (const float*)d_in[1];
    const float* enc       = (const float*)d_in[2];
    const float* embedding = (const float*)d_in[3];
    const float* attn_W    = (const float*)d_in[4];
    const float* attn_b    = (const float*)d_in[5];
    const float* comb_W    = (const float*)d_in[6];
    const float* comb_b    = (const float*)d_in[7];
    const float* w_ih      = (const float*)d_in[8];
    const float* w_hh      = (const float*)d_in[9];
    const float* b_ih      = (const float*)d_in[10];
    const float* b_hh      = (const float*)d_in[11];
    const float* out_W     = (const float*)d_in[12];
    const float* out_b     = (const float*)d_in[13];

    float* out = (float*)d_out;
    float* out_logits = out;
    float* out_h      = out + V;
    float* out_aw     = out + V + H;

    k_attn_scores<<<L / 8, 256>>>(token, hidden, embedding, attn_W, attn_b);
    k_context<<<64, 256>>>(enc, out_aw);
    k_combine<<<H / 8, 256>>>(token, embedding, comb_W, comb_b);
    k_gates<<<NB_GATES, 256>>>(w_ih, w_hh, b_ih, b_hh, hidden);
    k_hnew<<<H / 256, 256>>>(hidden, out_h);
    k_logits<<<NB_LOGITS, 256>>>(out_W, out_b, out_logits);
    k_logsoftmax<<<(V + 255) / 256, 256>>>(out_logits);
}